// round 1
// baseline (speedup 1.0000x reference)
#include <cuda_runtime.h>
#include <math.h>

#define NN 50000
#define EE 1600000
#define FF 64
#define HH 128
#define AA 16
#define NB 49            // ceil(NN/1024)

// ---------------- scratch (device globals; no allocation allowed) ----------
__device__ __align__(16) float g_h[NN * HH];      // h = X @ W (current layer)
__device__ __align__(16) float g_out[NN * HH];    // layer output
__device__ float g_ssrc[NN];
__device__ float g_sdst[NN];
__device__ int   g_cnt[NN];
__device__ __align__(16) float g_easum[NN * 2];   // -> ea_mean after scan3
__device__ int   g_rowptr[NN + 1];
__device__ int   g_writeptr[NN];
__device__ int   g_permsrc[EE];
__device__ __align__(16) float g_eaperm[EE * 2];
__device__ int   g_bsum[64];
__device__ int   g_boff[64];
__device__ float g_v[4];                          // We1@ae1 (2), We2@ae2 (2)
__device__ float g_pooled[HH];

// ---------------- init ------------------------------------------------------
__global__ void k_zero() {
    int i = blockIdx.x * blockDim.x + threadIdx.x;
    if (i < NN)      g_cnt[i] = 0;
    if (i < NN * 2)  g_easum[i] = 0.f;
    if (i < HH)      g_pooled[i] = 0.f;
}

// count in-degree + sum edge_attr per dst (for self-loop fill_value='mean')
__global__ void k_count(const int* __restrict__ ei, const float* __restrict__ ea) {
    int e = blockIdx.x * blockDim.x + threadIdx.x;
    if (e >= EE) return;
    int d = ei[EE + e];
    atomicAdd(&g_cnt[d], 1);
    atomicAdd(&g_easum[2 * d + 0], ea[2 * e + 0]);
    atomicAdd(&g_easum[2 * d + 1], ea[2 * e + 1]);
}

// ---------------- exclusive scan of g_cnt -> g_rowptr -----------------------
__global__ void k_scan1() {
    __shared__ int s[1024];
    int tid = threadIdx.x;
    int i = blockIdx.x * 1024 + tid;
    int c = (i < NN) ? g_cnt[i] : 0;
    s[tid] = c;
    __syncthreads();
    for (int off = 1; off < 1024; off <<= 1) {
        int t = (tid >= off) ? s[tid - off] : 0;
        __syncthreads();
        s[tid] += t;
        __syncthreads();
    }
    if (i < NN) g_rowptr[i] = s[tid] - c;   // exclusive, block-local
    if (tid == 1023) g_bsum[blockIdx.x] = s[1023];
}

__global__ void k_scan2() {
    if (threadIdx.x == 0) {
        int acc = 0;
        for (int b = 0; b < NB; b++) { g_boff[b] = acc; acc += g_bsum[b]; }
    }
}

__global__ void k_scan3() {
    int i = blockIdx.x * 1024 + threadIdx.x;
    if (i < NN) {
        int r = g_rowptr[i] + g_boff[blockIdx.x];
        g_rowptr[i] = r;
        g_writeptr[i] = r;
        float c = fmaxf((float)g_cnt[i], 1.f);
        g_easum[2 * i]     = g_easum[2 * i]     / c;   // ea_mean
        g_easum[2 * i + 1] = g_easum[2 * i + 1] / c;
    }
    if (i == 0) g_rowptr[NN] = EE;
}

// scatter edges into dst-sorted CSR
__global__ void k_scatter(const int* __restrict__ ei, const float* __restrict__ ea) {
    int e = blockIdx.x * blockDim.x + threadIdx.x;
    if (e >= EE) return;
    int d = ei[EE + e];
    int pos = atomicAdd(&g_writeptr[d], 1);
    g_permsrc[pos] = ei[e];
    g_eaperm[2 * pos + 0] = ea[2 * e + 0];
    g_eaperm[2 * pos + 1] = ea[2 * e + 1];
}

// v = We @ a_e for both layers (ED=2)
__global__ void k_v(const float* __restrict__ We1, const float* __restrict__ ae1,
                    const float* __restrict__ We2, const float* __restrict__ ae2) {
    __shared__ float red[128];
    int t = threadIdx.x;
    float vals[4] = { We1[t] * ae1[t], We1[128 + t] * ae1[t],
                      We2[t] * ae2[t], We2[128 + t] * ae2[t] };
    for (int k = 0; k < 4; k++) {
        red[t] = vals[k];
        __syncthreads();
        for (int off = 64; off > 0; off >>= 1) {
            if (t < off) red[t] += red[t + off];
            __syncthreads();
        }
        if (t == 0) g_v[k] = red[0];
        __syncthreads();
    }
}

// ---------------- SGEMM: g_h = X[N,K] @ W[K,128] ---------------------------
template <int K>
__global__ __launch_bounds__(256) void k_gemm(const float* __restrict__ X,
                                              const float* __restrict__ W) {
    __shared__ float As[16][64];
    __shared__ float Bs[16][128];
    int tid = threadIdx.x;
    int r0 = blockIdx.x * 64;
    int tx = tid & 15, ty = tid >> 4;       // tx: col group (8), ty: row group (4)
    float acc[4][8];
#pragma unroll
    for (int i = 0; i < 4; i++)
#pragma unroll
        for (int j = 0; j < 8; j++) acc[i][j] = 0.f;

    int lr = tid >> 2;            // 0..63
    int lc = (tid & 3) * 4;       // 0,4,8,12
    int wr = tid >> 4;            // 0..15
    int wc = (tid & 15) * 8;      // 0..120

    for (int k0 = 0; k0 < K; k0 += 16) {
        float4 xa = make_float4(0.f, 0.f, 0.f, 0.f);
        if (r0 + lr < NN) xa = *(const float4*)&X[(r0 + lr) * K + k0 + lc];
        As[lc + 0][lr] = xa.x; As[lc + 1][lr] = xa.y;
        As[lc + 2][lr] = xa.z; As[lc + 3][lr] = xa.w;
        float4 w0 = *(const float4*)&W[(k0 + wr) * HH + wc];
        float4 w1 = *(const float4*)&W[(k0 + wr) * HH + wc + 4];
        *(float4*)&Bs[wr][wc] = w0;
        *(float4*)&Bs[wr][wc + 4] = w1;
        __syncthreads();
#pragma unroll
        for (int kk = 0; kk < 16; kk++) {
            float a0 = As[kk][ty * 4 + 0], a1 = As[kk][ty * 4 + 1];
            float a2 = As[kk][ty * 4 + 2], a3 = As[kk][ty * 4 + 3];
            float b[8];
#pragma unroll
            for (int j = 0; j < 8; j++) b[j] = Bs[kk][tx * 8 + j];
#pragma unroll
            for (int j = 0; j < 8; j++) {
                acc[0][j] += a0 * b[j]; acc[1][j] += a1 * b[j];
                acc[2][j] += a2 * b[j]; acc[3][j] += a3 * b[j];
            }
        }
        __syncthreads();
    }
#pragma unroll
    for (int i = 0; i < 4; i++) {
        int row = r0 + ty * 4 + i;
        if (row < NN) {
            float4 o0 = make_float4(acc[i][0], acc[i][1], acc[i][2], acc[i][3]);
            float4 o1 = make_float4(acc[i][4], acc[i][5], acc[i][6], acc[i][7]);
            *(float4*)&g_h[row * HH + tx * 8]     = o0;
            *(float4*)&g_h[row * HH + tx * 8 + 4] = o1;
        }
    }
}

// per-node attention dots: s_src = h.a_s, s_dst = h.a_d  (one warp / node)
__global__ void k_dots(const float* __restrict__ as_, const float* __restrict__ ad_) {
    int warp = (blockIdx.x * blockDim.x + threadIdx.x) >> 5;
    int lane = threadIdx.x & 31;
    if (warp >= NN) return;
    float4 h4 = *(const float4*)&g_h[warp * HH + lane * 4];
    float4 a4 = *(const float4*)&as_[lane * 4];
    float4 d4 = *(const float4*)&ad_[lane * 4];
    float ss = h4.x * a4.x + h4.y * a4.y + h4.z * a4.z + h4.w * a4.w;
    float sd = h4.x * d4.x + h4.y * d4.y + h4.z * d4.z + h4.w * d4.w;
#pragma unroll
    for (int off = 16; off; off >>= 1) {
        ss += __shfl_xor_sync(0xffffffffu, ss, off);
        sd += __shfl_xor_sync(0xffffffffu, sd, off);
    }
    if (lane == 0) { g_ssrc[warp] = ss; g_sdst[warp] = sd; }
}

__device__ __forceinline__ float lrelu(float x) { return x > 0.f ? x : 0.2f * x; }

// fused GAT aggregation: one warp per node, atomic-free (CSR gather)
__global__ __launch_bounds__(256) void k_gat(const float* __restrict__ bias, int voff) {
    int warp = (blockIdx.x * blockDim.x + threadIdx.x) >> 5;
    int lane = threadIdx.x & 31;
    if (warp >= NN) return;
    int n = warp;
    float v0 = g_v[voff], v1 = g_v[voff + 1];
    int rp0 = g_rowptr[n], rp1 = g_rowptr[n + 1];
    float sd = g_sdst[n];

    // self-loop logit (edge_attr = per-dst mean)
    float selfl = lrelu(g_ssrc[n] + sd + g_easum[2 * n] * v0 + g_easum[2 * n + 1] * v1);

    // pass 1: segment max
    float m = selfl;
    for (int i = rp0 + lane; i < rp1; i += 32) {
        float lg = lrelu(g_ssrc[g_permsrc[i]] + sd
                         + g_eaperm[2 * i] * v0 + g_eaperm[2 * i + 1] * v1);
        m = fmaxf(m, lg);
    }
#pragma unroll
    for (int off = 16; off; off >>= 1) m = fmaxf(m, __shfl_xor_sync(0xffffffffu, m, off));

    // pass 2: fused exp + weighted h-gather accumulation
    float p_self = __expf(selfl - m);
    float4 hn = *(const float4*)&g_h[n * HH + lane * 4];
    float4 acc = make_float4(p_self * hn.x, p_self * hn.y, p_self * hn.z, p_self * hn.w);
    float denom = (lane == 0) ? p_self : 0.f;

    for (int start = rp0; start < rp1; start += 32) {
        int i = start + lane;
        float p = 0.f;
        int s = 0;
        if (i < rp1) {
            s = g_permsrc[i];
            float lg = lrelu(g_ssrc[s] + sd
                             + g_eaperm[2 * i] * v0 + g_eaperm[2 * i + 1] * v1);
            p = __expf(lg - m);
        }
        denom += p;
        int cnt = min(32, rp1 - start);
        for (int j = 0; j < cnt; j++) {
            float pj = __shfl_sync(0xffffffffu, p, j);
            int sj = __shfl_sync(0xffffffffu, s, j);
            float4 hv = *(const float4*)&g_h[sj * HH + lane * 4];
            acc.x += pj * hv.x; acc.y += pj * hv.y;
            acc.z += pj * hv.z; acc.w += pj * hv.w;
        }
    }
#pragma unroll
    for (int off = 16; off; off >>= 1) denom += __shfl_xor_sync(0xffffffffu, denom, off);
    float inv = 1.f / (denom + 1e-16f);

    float4 bb = *(const float4*)&bias[lane * 4];
    float4 o;
    o.x = fmaxf(acc.x * inv + bb.x, 0.f);
    o.y = fmaxf(acc.y * inv + bb.y, 0.f);
    o.z = fmaxf(acc.z * inv + bb.z, 0.f);
    o.w = fmaxf(acc.w * inv + bb.w, 0.f);
    *(float4*)&g_out[n * HH + lane * 4] = o;
}

// column-sum over rows (mean pool numerator)
__global__ void k_pool() {
    int t = threadIdx.x;
    int r0 = blockIdx.x * 128;
    int r1 = min(r0 + 128, NN);
    float acc = 0.f;
    for (int r = r0; r < r1; r++) acc += g_out[r * HH + t];
    atomicAdd(&g_pooled[t], acc);
}

// final head: out[a] = tanh(mean_pooled @ Wfc[:,a] + bfc[a])
__global__ void k_head(const float* __restrict__ Wfc, const float* __restrict__ bfc,
                       float* __restrict__ out) {
    int warp = threadIdx.x >> 5;   // 16 warps = AA outputs
    int lane = threadIdx.x & 31;
    float sum = 0.f;
    for (int h = lane; h < HH; h += 32) sum += g_pooled[h] * Wfc[h * AA + warp];
#pragma unroll
    for (int off = 16; off; off >>= 1) sum += __shfl_xor_sync(0xffffffffu, sum, off);
    if (lane == 0) out[warp] = tanhf(sum * (1.0f / NN) + bfc[warp]);
}

// ---------------- launch ----------------------------------------------------
extern "C" void kernel_launch(void* const* d_in, const int* in_sizes, int n_in,
                              void* d_out, int out_size) {
    const float* x      = (const float*)d_in[0];
    const int*   ei     = (const int*)d_in[1];
    const float* ea     = (const float*)d_in[2];
    const float* W1     = (const float*)d_in[3];
    const float* We1    = (const float*)d_in[4];
    const float* asrc1  = (const float*)d_in[5];
    const float* adst1  = (const float*)d_in[6];
    const float* aedge1 = (const float*)d_in[7];
    const float* b1     = (const float*)d_in[8];
    const float* W2     = (const float*)d_in[9];
    const float* We2    = (const float*)d_in[10];
    const float* asrc2  = (const float*)d_in[11];
    const float* adst2  = (const float*)d_in[12];
    const float* aedge2 = (const float*)d_in[13];
    const float* b2     = (const float*)d_in[14];
    const float* Wfc    = (const float*)d_in[15];
    const float* bfc    = (const float*)d_in[16];
    float* out = (float*)d_out;

    void* outbuf_p = nullptr;
    cudaGetSymbolAddress(&outbuf_p, g_out);
    const float* g_out_h = (const float*)outbuf_p;

    const int EB = (EE + 255) / 256;
    const int NWB = (NN * 32) / 256;   // 6250: one warp per node

    k_zero<<<(NN * 2 + 255) / 256, 256>>>();
    k_count<<<EB, 256>>>(ei, ea);
    k_scan1<<<NB, 1024>>>();
    k_scan2<<<1, 32>>>();
    k_scan3<<<NB, 1024>>>();
    k_scatter<<<EB, 256>>>(ei, ea);
    k_v<<<1, 128>>>(We1, aedge1, We2, aedge2);

    // layer 1
    k_gemm<FF><<<(NN + 63) / 64, 256>>>(x, W1);
    k_dots<<<NWB, 256>>>(asrc1, adst1);
    k_gat<<<NWB, 256>>>(b1, 0);

    // layer 2
    k_gemm<HH><<<(NN + 63) / 64, 256>>>(g_out_h, W2);
    k_dots<<<NWB, 256>>>(asrc2, adst2);
    k_gat<<<NWB, 256>>>(b2, 2);

    // pool + head
    k_pool<<<(NN + 127) / 128, 128>>>();
    k_head<<<1, 512>>>(Wfc, bfc, out);
}

// round 2
// speedup vs baseline: 1.1619x; 1.1619x over previous
#include <cuda_runtime.h>
#include <cuda_bf16.h>
#include <math.h>

#define NN 50000
#define EE 1600000
#define FF 64
#define HH 128
#define AA 16
#define NB 49            // ceil(NN/1024)

// ---------------- scratch (device globals; no allocation allowed) ----------
__device__ __align__(16) __nv_bfloat16 g_hb[NN * HH];  // h in bf16 (gather operand)
__device__ __align__(16) float g_out[NN * HH];         // layer output (fp32)
__device__ float g_ssrc[NN];
__device__ float g_sdst[NN];
__device__ int   g_cnt[NN];
__device__ __align__(16) float g_easum[NN * 2];   // -> self-loop ea.v per layer after scan3
__device__ int   g_rowptr[NN + 1];
__device__ int   g_writeptr[NN];
__device__ int   g_permsrc[EE];
__device__ float g_eac1[EE];                      // per-edge ea.v (layer 1)
__device__ float g_eac2[EE];                      // per-edge ea.v (layer 2)
__device__ int   g_bsum[64];
__device__ int   g_boff[64];
__device__ float g_v[4];                          // We1@ae1 (2), We2@ae2 (2)
__device__ float g_pooled[HH];

// ---------------- init ------------------------------------------------------
__global__ void k_zero() {
    int i = blockIdx.x * blockDim.x + threadIdx.x;
    if (i < NN)      g_cnt[i] = 0;
    if (i < NN * 2)  g_easum[i] = 0.f;
    if (i < HH)      g_pooled[i] = 0.f;
}

// v = We @ a_e for both layers (ED=2)
__global__ void k_v(const float* __restrict__ We1, const float* __restrict__ ae1,
                    const float* __restrict__ We2, const float* __restrict__ ae2) {
    __shared__ float red[128];
    int t = threadIdx.x;
    float vals[4] = { We1[t] * ae1[t], We1[128 + t] * ae1[t],
                      We2[t] * ae2[t], We2[128 + t] * ae2[t] };
    for (int k = 0; k < 4; k++) {
        red[t] = vals[k];
        __syncthreads();
        for (int off = 64; off > 0; off >>= 1) {
            if (t < off) red[t] += red[t + off];
            __syncthreads();
        }
        if (t == 0) g_v[k] = red[0];
        __syncthreads();
    }
}

// count in-degree + sum edge_attr per dst (for self-loop fill_value='mean')
__global__ void k_count(const int* __restrict__ ei, const float* __restrict__ ea) {
    int e = blockIdx.x * blockDim.x + threadIdx.x;
    if (e >= EE) return;
    int d = ei[EE + e];
    atomicAdd(&g_cnt[d], 1);
    atomicAdd(&g_easum[2 * d + 0], ea[2 * e + 0]);
    atomicAdd(&g_easum[2 * d + 1], ea[2 * e + 1]);
}

// ---------------- exclusive scan of g_cnt -> g_rowptr -----------------------
__global__ void k_scan1() {
    __shared__ int s[1024];
    int tid = threadIdx.x;
    int i = blockIdx.x * 1024 + tid;
    int c = (i < NN) ? g_cnt[i] : 0;
    s[tid] = c;
    __syncthreads();
    for (int off = 1; off < 1024; off <<= 1) {
        int t = (tid >= off) ? s[tid - off] : 0;
        __syncthreads();
        s[tid] += t;
        __syncthreads();
    }
    if (i < NN) g_rowptr[i] = s[tid] - c;   // exclusive, block-local
    if (tid == 1023) g_bsum[blockIdx.x] = s[1023];
}

__global__ void k_scan2() {
    __shared__ int s[64];
    int t = threadIdx.x;
    int c = (t < NB) ? g_bsum[t] : 0;
    s[t] = c;
    __syncthreads();
    for (int off = 1; off < 64; off <<= 1) {
        int v = (t >= off) ? s[t - off] : 0;
        __syncthreads();
        s[t] += v;
        __syncthreads();
    }
    if (t < NB) g_boff[t] = s[t] - c;       // exclusive
}

// finalize rowptr + compute self-loop ea.v contribution for both layers
__global__ void k_scan3() {
    int i = blockIdx.x * 1024 + threadIdx.x;
    if (i < NN) {
        int r = g_rowptr[i] + g_boff[blockIdx.x];
        g_rowptr[i] = r;
        g_writeptr[i] = r;
        float c = fmaxf((float)g_cnt[i], 1.f);
        float m0 = g_easum[2 * i]     / c;        // ea_mean
        float m1 = g_easum[2 * i + 1] / c;
        g_easum[2 * i]     = m0 * g_v[0] + m1 * g_v[1];  // layer-1 self ea.v
        g_easum[2 * i + 1] = m0 * g_v[2] + m1 * g_v[3];  // layer-2 self ea.v
    }
    if (i == 0) g_rowptr[NN] = EE;
}

// scatter edges into dst-sorted CSR; precompute ea.v per edge per layer
__global__ void k_scatter(const int* __restrict__ ei, const float* __restrict__ ea) {
    int e = blockIdx.x * blockDim.x + threadIdx.x;
    if (e >= EE) return;
    int d = ei[EE + e];
    float e0 = ea[2 * e + 0], e1 = ea[2 * e + 1];
    int pos = atomicAdd(&g_writeptr[d], 1);
    g_permsrc[pos] = ei[e];
    g_eac1[pos] = e0 * g_v[0] + e1 * g_v[1];
    g_eac2[pos] = e0 * g_v[2] + e1 * g_v[3];
}

// ---------------- SGEMM: h = X[N,K] @ W[K,128]  (+ fused dots + bf16 store)
template <int K>
__global__ __launch_bounds__(256) void k_gemm(const float* __restrict__ X,
                                              const float* __restrict__ W,
                                              const float* __restrict__ as_,
                                              const float* __restrict__ ad_) {
    __shared__ float As[16][64];
    __shared__ float Bs[16][128];
    int tid = threadIdx.x;
    int r0 = blockIdx.x * 64;
    int tx = tid & 15, ty = tid >> 4;       // tx: col group (8 cols), ty: row group (4 rows)
    float acc[4][8];
#pragma unroll
    for (int i = 0; i < 4; i++)
#pragma unroll
        for (int j = 0; j < 8; j++) acc[i][j] = 0.f;

    int lr = tid >> 2;            // 0..63
    int lc = (tid & 3) * 4;       // 0,4,8,12
    int wr = tid >> 4;            // 0..15
    int wc = (tid & 15) * 8;      // 0..120

    for (int k0 = 0; k0 < K; k0 += 16) {
        float4 xa = make_float4(0.f, 0.f, 0.f, 0.f);
        if (r0 + lr < NN) xa = *(const float4*)&X[(r0 + lr) * K + k0 + lc];
        As[lc + 0][lr] = xa.x; As[lc + 1][lr] = xa.y;
        As[lc + 2][lr] = xa.z; As[lc + 3][lr] = xa.w;
        float4 w0 = *(const float4*)&W[(k0 + wr) * HH + wc];
        float4 w1 = *(const float4*)&W[(k0 + wr) * HH + wc + 4];
        *(float4*)&Bs[wr][wc] = w0;
        *(float4*)&Bs[wr][wc + 4] = w1;
        __syncthreads();
#pragma unroll
        for (int kk = 0; kk < 16; kk++) {
            float a0 = As[kk][ty * 4 + 0], a1 = As[kk][ty * 4 + 1];
            float a2 = As[kk][ty * 4 + 2], a3 = As[kk][ty * 4 + 3];
            float b[8];
#pragma unroll
            for (int j = 0; j < 8; j++) b[j] = Bs[kk][tx * 8 + j];
#pragma unroll
            for (int j = 0; j < 8; j++) {
                acc[0][j] += a0 * b[j]; acc[1][j] += a1 * b[j];
                acc[2][j] += a2 * b[j]; acc[3][j] += a3 * b[j];
            }
        }
        __syncthreads();
    }

    // epilogue: bf16 store + attention dot partials
    float4 as0 = *(const float4*)&as_[tx * 8];
    float4 as1 = *(const float4*)&as_[tx * 8 + 4];
    float4 ad0 = *(const float4*)&ad_[tx * 8];
    float4 ad1 = *(const float4*)&ad_[tx * 8 + 4];
#pragma unroll
    for (int i = 0; i < 4; i++) {
        int row = r0 + ty * 4 + i;
        float ps = 0.f, pd = 0.f;
        if (row < NN) {
            __nv_bfloat162 p0 = __floats2bfloat162_rn(acc[i][0], acc[i][1]);
            __nv_bfloat162 p1 = __floats2bfloat162_rn(acc[i][2], acc[i][3]);
            __nv_bfloat162 p2 = __floats2bfloat162_rn(acc[i][4], acc[i][5]);
            __nv_bfloat162 p3 = __floats2bfloat162_rn(acc[i][6], acc[i][7]);
            uint4 pk;
            pk.x = *(unsigned*)&p0; pk.y = *(unsigned*)&p1;
            pk.z = *(unsigned*)&p2; pk.w = *(unsigned*)&p3;
            *(uint4*)&g_hb[row * HH + tx * 8] = pk;
            ps = acc[i][0] * as0.x + acc[i][1] * as0.y + acc[i][2] * as0.z + acc[i][3] * as0.w
               + acc[i][4] * as1.x + acc[i][5] * as1.y + acc[i][6] * as1.z + acc[i][7] * as1.w;
            pd = acc[i][0] * ad0.x + acc[i][1] * ad0.y + acc[i][2] * ad0.z + acc[i][3] * ad0.w
               + acc[i][4] * ad1.x + acc[i][5] * ad1.y + acc[i][6] * ad1.z + acc[i][7] * ad1.w;
        }
#pragma unroll
        for (int off = 1; off < 16; off <<= 1) {
            ps += __shfl_xor_sync(0xffffffffu, ps, off);
            pd += __shfl_xor_sync(0xffffffffu, pd, off);
        }
        if (tx == 0 && row < NN) { g_ssrc[row] = ps; g_sdst[row] = pd; }
    }
}

__device__ __forceinline__ float lrelu(float x) { return x > 0.f ? x : 0.2f * x; }

// fused GAT aggregation: one warp per node, single-pass online softmax,
// bf16 h gathers, fp32 accumulation.
__global__ __launch_bounds__(256) void k_gat(const float* __restrict__ bias, int layer) {
    int warp = (blockIdx.x * blockDim.x + threadIdx.x) >> 5;
    int lane = threadIdx.x & 31;
    if (warp >= NN) return;
    int n = warp;
    const float* eac = (layer == 0) ? g_eac1 : g_eac2;
    int rp0 = g_rowptr[n], rp1 = g_rowptr[n + 1];
    float sd = g_sdst[n];

    // self-loop logit (edge_attr = per-dst mean; ea.v precomputed in scan3)
    float selfl = lrelu(g_ssrc[n] + sd + g_easum[2 * n + layer]);

    // init with self edge: running max m = selfl -> p_self = 1
    float m = selfl;
    uint2 hu = *(const uint2*)&g_hb[n * HH + lane * 4];
    float2 h0 = __bfloat1622float2(*(__nv_bfloat162*)&hu.x);
    float2 h1 = __bfloat1622float2(*(__nv_bfloat162*)&hu.y);
    float4 acc = make_float4(h0.x, h0.y, h1.x, h1.y);
    float denom = (lane == 0) ? 1.f : 0.f;

    for (int start = rp0; start < rp1; start += 32) {
        int i = start + lane;
        float lg = -3.4e38f;
        int s = 0;
        if (i < rp1) {
            s = g_permsrc[i];
            lg = lrelu(g_ssrc[s] + sd + eac[i]);
        }
        // warp-wide batch max, online rescale
        float bm = lg;
#pragma unroll
        for (int off = 16; off; off >>= 1) bm = fmaxf(bm, __shfl_xor_sync(0xffffffffu, bm, off));
        if (bm > m) {
            float scale = __expf(m - bm);
            acc.x *= scale; acc.y *= scale; acc.z *= scale; acc.w *= scale;
            denom *= scale;
            m = bm;
        }
        float p = (i < rp1) ? __expf(lg - m) : 0.f;
        denom += p;
        int cnt = min(32, rp1 - start);
        for (int j = 0; j < cnt; j++) {
            float pj = __shfl_sync(0xffffffffu, p, j);
            int sj = __shfl_sync(0xffffffffu, s, j);
            uint2 u = *(const uint2*)&g_hb[sj * HH + lane * 4];
            float2 f0 = __bfloat1622float2(*(__nv_bfloat162*)&u.x);
            float2 f1 = __bfloat1622float2(*(__nv_bfloat162*)&u.y);
            acc.x += pj * f0.x; acc.y += pj * f0.y;
            acc.z += pj * f1.x; acc.w += pj * f1.y;
        }
    }
#pragma unroll
    for (int off = 16; off; off >>= 1) denom += __shfl_xor_sync(0xffffffffu, denom, off);
    float inv = 1.f / (denom + 1e-16f);

    float4 bb = *(const float4*)&bias[lane * 4];
    float4 o;
    o.x = fmaxf(acc.x * inv + bb.x, 0.f);
    o.y = fmaxf(acc.y * inv + bb.y, 0.f);
    o.z = fmaxf(acc.z * inv + bb.z, 0.f);
    o.w = fmaxf(acc.w * inv + bb.w, 0.f);
    *(float4*)&g_out[n * HH + lane * 4] = o;
}

// column-sum over rows (mean pool numerator)
__global__ void k_pool() {
    int t = threadIdx.x;
    int r0 = blockIdx.x * 128;
    int r1 = min(r0 + 128, NN);
    float acc = 0.f;
    for (int r = r0; r < r1; r++) acc += g_out[r * HH + t];
    atomicAdd(&g_pooled[t], acc);
}

// final head: out[a] = tanh(mean_pooled @ Wfc[:,a] + bfc[a])
__global__ void k_head(const float* __restrict__ Wfc, const float* __restrict__ bfc,
                       float* __restrict__ out) {
    int warp = threadIdx.x >> 5;   // 16 warps = AA outputs
    int lane = threadIdx.x & 31;
    float sum = 0.f;
    for (int h = lane; h < HH; h += 32) sum += g_pooled[h] * Wfc[h * AA + warp];
#pragma unroll
    for (int off = 16; off; off >>= 1) sum += __shfl_xor_sync(0xffffffffu, sum, off);
    if (lane == 0) out[warp] = tanhf(sum * (1.0f / NN) + bfc[warp]);
}

// ---------------- launch ----------------------------------------------------
extern "C" void kernel_launch(void* const* d_in, const int* in_sizes, int n_in,
                              void* d_out, int out_size) {
    const float* x      = (const float*)d_in[0];
    const int*   ei     = (const int*)d_in[1];
    const float* ea     = (const float*)d_in[2];
    const float* W1     = (const float*)d_in[3];
    const float* We1    = (const float*)d_in[4];
    const float* asrc1  = (const float*)d_in[5];
    const float* adst1  = (const float*)d_in[6];
    const float* aedge1 = (const float*)d_in[7];
    const float* b1     = (const float*)d_in[8];
    const float* W2     = (const float*)d_in[9];
    const float* We2    = (const float*)d_in[10];
    const float* asrc2  = (const float*)d_in[11];
    const float* adst2  = (const float*)d_in[12];
    const float* aedge2 = (const float*)d_in[13];
    const float* b2     = (const float*)d_in[14];
    const float* Wfc    = (const float*)d_in[15];
    const float* bfc    = (const float*)d_in[16];
    float* out = (float*)d_out;

    void* outbuf_p = nullptr;
    cudaGetSymbolAddress(&outbuf_p, g_out);
    const float* g_out_h = (const float*)outbuf_p;

    const int EB = (EE + 255) / 256;
    const int NWB = (NN * 32) / 256;   // 6250: one warp per node

    k_zero<<<(NN * 2 + 255) / 256, 256>>>();
    k_v<<<1, 128>>>(We1, aedge1, We2, aedge2);
    k_count<<<EB, 256>>>(ei, ea);
    k_scan1<<<NB, 1024>>>();
    k_scan2<<<1, 64>>>();
    k_scan3<<<NB, 1024>>>();
    k_scatter<<<EB, 256>>>(ei, ea);

    // layer 1
    k_gemm<FF><<<(NN + 63) / 64, 256>>>(x, W1, asrc1, adst1);
    k_gat<<<NWB, 256>>>(b1, 0);

    // layer 2
    k_gemm<HH><<<(NN + 63) / 64, 256>>>(g_out_h, W2, asrc2, adst2);
    k_gat<<<NWB, 256>>>(b2, 1);

    // pool + head
    k_pool<<<(NN + 127) / 128, 128>>>();
    k_head<<<1, 512>>>(Wfc, bfc, out);
}